// round 16
// baseline (speedup 1.0000x reference)
#include <cuda_runtime.h>

#define PN 16800
#define ON 64
#define BN 64
#define FULLMASK 0xffffffffu

// ---------------- scratch ----------------
__device__ unsigned long long g_bp[BN * ON];
__device__ float g_rank[BN * PN];
__device__ int g_npb[BN];
__device__ float g_acc[3];
__device__ int g_cnt[2];
__device__ int g_done;

// =================== helpers ===================
__device__ __forceinline__ float sl1(float x) {
    float a = fabsf(x);
    return a < 1.f ? 0.5f * a * a : a - 0.5f;
}
__device__ __forceinline__ float warp_sumf(float v) {
#pragma unroll
    for (int s = 16; s; s >>= 1) v += __shfl_xor_sync(FULLMASK, v, s);
    return v;
}
__device__ __forceinline__ int warp_sumi(int v) {
#pragma unroll
    for (int s = 16; s; s >>= 1) v += __shfl_xor_sync(FULLMASK, v, s);
    return v;
}

template<int NB>
__device__ __forceinline__ void select_desc(
    unsigned* hist, unsigned* s_wsum,
    int kr_in, int* s_kr, unsigned* s_sel,
    int tid, int lane, int warp)
{
    if (NB == 2048) {
        unsigned h0 = hist[2047 - 2 * tid];
        unsigned h1 = hist[2046 - 2 * tid];
        unsigned sv = h0 + h1, inc = sv;
#pragma unroll
        for (int d = 1; d < 32; d <<= 1) {
            unsigned ot = __shfl_up_sync(FULLMASK, inc, d);
            if (lane >= d) inc += ot;
        }
        if (lane == 31) s_wsum[warp] = inc;
        __syncthreads();
        if (tid < 32) {
            unsigned w = s_wsum[tid], wi = w;
#pragma unroll
            for (int d = 1; d < 32; d <<= 1) {
                unsigned ot = __shfl_up_sync(FULLMASK, wi, d);
                if (tid >= d) wi += ot;
            }
            s_wsum[tid] = wi - w;
        }
        __syncthreads();
        unsigned excl = s_wsum[warp] + (inc - sv);
        unsigned kr = (unsigned)kr_in;
        bool x0 = (excl < kr) && (excl + h0 >= kr);
        bool x1 = (excl + h0 < kr) && (excl + h0 + h1 >= kr);
        __syncthreads();
        if (x0) { *s_kr = (int)(kr - excl); *s_sel = (unsigned)(2047 - 2 * tid); }
        if (x1) { *s_kr = (int)(kr - excl - h0); *s_sel = (unsigned)(2046 - 2 * tid); }
        __syncthreads();
    } else {
        unsigned h0 = hist[1023 - tid];
        unsigned inc = h0;
#pragma unroll
        for (int d = 1; d < 32; d <<= 1) {
            unsigned ot = __shfl_up_sync(FULLMASK, inc, d);
            if (lane >= d) inc += ot;
        }
        if (lane == 31) s_wsum[warp] = inc;
        __syncthreads();
        if (tid < 32) {
            unsigned w = s_wsum[tid], wi = w;
#pragma unroll
            for (int d = 1; d < 32; d <<= 1) {
                unsigned ot = __shfl_up_sync(FULLMASK, wi, d);
                if (tid >= d) wi += ot;
            }
            s_wsum[tid] = wi - w;
        }
        __syncthreads();
        unsigned excl = s_wsum[warp] + (inc - h0);
        unsigned kr = (unsigned)kr_in;
        bool x0 = (excl < kr) && (excl + h0 >= kr);
        __syncthreads();
        if (x0) { *s_kr = (int)(kr - excl); *s_sel = (unsigned)(1023 - tid); }
        __syncthreads();
    }
}

// =================== k_pre: best-prior per truth + resets ===================
__global__ void __launch_bounds__(256) k_pre(
    const float4* __restrict__ priors,
    const float* __restrict__ targets)
{
    const int b = blockIdx.x;
    const int tid = threadIdx.x;
    const int lane = tid & 31;
    const int wid = tid >> 5;

    __shared__ float tX1[ON], tX2[ON], tY1[ON], tY2[ON], tA[ON];
    __shared__ float b_px1[280], b_px2[280], b_py1[280], b_py2[280];

    if (tid < ON) {
        const float* t = targets + (size_t)(b * ON + tid) * 15;
        float x1 = t[0], y1 = t[1], x2 = t[2], y2 = t[3];
        tX1[tid] = x1; tY1[tid] = y1; tX2[tid] = x2; tY2[tid] = y2;
        tA[tid] = (x2 - x1) * (y2 - y1);
    }
    if (tid < 3) g_acc[tid] = 0.f;
    if (tid >= 3 && tid < 5) g_cnt[tid - 3] = 0;
    if (tid == 5) g_npb[b] = 0;

    for (int t = tid; t < 280; t += 256) {
        int g = (t < 80) ? 0 : (t < 160) ? 1 : (t < 200) ? 2 : (t < 240) ? 3 : (t < 260) ? 4 : 5;
        int off = (g == 0) ? 0 : (g == 1) ? 80 : (g == 2) ? 160 : (g == 3) ? 200 : (g == 4) ? 240 : 260;
        int f = (g < 2) ? 80 : (g < 4) ? 40 : 20;
        int base = (g == 0) ? 0 : (g == 1) ? 6400 : (g == 2) ? 12800 :
                   (g == 3) ? 14400 : (g == 4) ? 16000 : 16400;
        int j = t - off;
        float4 q = priors[base + j];
        b_px1[t] = q.x - q.z * 0.5f; b_px2[t] = q.x + q.z * 0.5f;
        float4 qy = priors[base + j * f];
        b_py1[t] = qy.y - qy.w * 0.5f; b_py2[t] = qy.y + qy.w * 0.5f;
    }
    __syncthreads();

    const int GF[6]   = {80, 80, 40, 40, 20, 20};
    const int GBASE[6]= {0, 6400, 12800, 14400, 16000, 16400};
    const int GOFF[6] = {0, 80, 160, 200, 240, 260};

    for (int it = 0; it < 8; it++) {
        const int o = wid * 8 + it;
        const float X1 = tX1[o], X2 = tX2[o], Y1 = tY1[o], Y2 = tY2[o], A = tA[o];
        unsigned long long best = 0ull;
#pragma unroll
        for (int g = 0; g < 6; g++) {
            const int f = GF[g], co = GOFF[g], base = GBASE[g];
            float bwx = -1.f; int bj = lane;
            for (int j = lane; j < f; j += 32) {
                float v = fmaxf(fminf(X2, b_px2[co + j]) - fmaxf(X1, b_px1[co + j]), 0.f);
                if (v > bwx) { bwx = v; bj = j; }
            }
            float bwy = -1.f; int bi2 = lane;
            for (int i = lane; i < f; i += 32) {
                float v = fmaxf(fminf(Y2, b_py2[co + i]) - fmaxf(Y1, b_py1[co + i]), 0.f);
                if (v > bwy) { bwy = v; bi2 = i; }
            }
#pragma unroll
            for (int s = 16; s; s >>= 1) {
                float ov = __shfl_xor_sync(FULLMASK, bwx, s);
                int oj = __shfl_xor_sync(FULLMASK, bj, s);
                if (ov > bwx || (ov == bwx && oj < bj)) { bwx = ov; bj = oj; }
                float ov2 = __shfl_xor_sync(FULLMASK, bwy, s);
                int oi = __shfl_xor_sync(FULLMASK, bi2, s);
                if (ov2 > bwy || (ov2 == bwy && oi < bi2)) { bwy = ov2; bi2 = oi; }
            }
            float P = bwx * bwy;
            float dx = b_px2[co + bj] - b_px1[co + bj];
            float dy = b_py2[co + bi2] - b_py1[co + bi2];
            float den = (A + dx * dy) - P;
            float iou = __fdiv_rn(P, den);
            unsigned pidx = (unsigned)(base + bi2 * f + bj);
            unsigned long long key =
                ((unsigned long long)__float_as_uint(iou) << 32) |
                (unsigned long long)(0xFFFFFFFFu - pidx);
            if (key > best) best = key;
        }
        if (lane == 0) g_bp[b * ON + o] = best;
    }
}

// =================== k_fused: match tiles + inline loss phase A ===========
__global__ void __launch_bounds__(256) k_fused(
    const float* __restrict__ loc,
    const float* __restrict__ conf,
    const float* __restrict__ landm,
    const float4* __restrict__ priors,
    const float* __restrict__ targets)
{
    const int b = blockIdx.y;
    const int bx = blockIdx.x;
    const int tid = threadIdx.x;
    const int lane = tid & 31;
    const int wid = tid >> 5;

    int g, blk;
    if (bx < 7)       { g = 0; blk = bx; }
    else if (bx < 14) { g = 1; blk = bx - 7; }
    else if (bx < 16) { g = 2; blk = bx - 14; }
    else if (bx < 18) { g = 3; blk = bx - 16; }
    else if (bx == 18){ g = 4; blk = 0; }
    else              { g = 5; blk = 0; }
    const int f    = (g < 2) ? 80 : (g < 4) ? 40 : 20;
    const int base = (g == 0) ? 0 : (g == 1) ? 6400 : (g == 2) ? 12800 :
                     (g == 3) ? 14400 : (g == 4) ? 16000 : 16400;
    const int off  = blk * 1024;
    const int n    = min(1024, f * f - off);
    const int i0   = off / f;
    const int nrows = (off + n - 1) / f - i0 + 1;
    const int pg0  = base + off;        // block's contiguous global prior range

    __shared__ float tX1[ON], tX2[ON], tY1[ON], tY2[ON], tA[ON];
    __shared__ float s_wx[ON * 80];
    __shared__ float s_wyc[ON * 28];
    __shared__ float s_C[ON];
    __shared__ float s_px1[80], s_px2[80], s_dx[80];
    __shared__ float s_py1[28], s_py2[28], s_dy[28];
    __shared__ float s_t[ON * 4];
    __shared__ float s_lm[ON * 10];
    __shared__ int s_lab[ON];
    __shared__ unsigned s_js[ON];
    __shared__ int s_vld[ON];
    __shared__ unsigned s_bmp[32];
    __shared__ unsigned s_anyb[2];
    __shared__ int cO[ON];
    __shared__ int s_cnt;
    __shared__ float r_ll, r_lm, r_ce;
    __shared__ int r_np, r_np1;

    if (tid < 32) s_bmp[tid] = 0;
    if (tid == 0) { r_ll = 0.f; r_lm = 0.f; r_ce = 0.f; r_np = 0; r_np1 = 0; }

    if (tid < ON) {
        const float* t = targets + (size_t)(b * ON + tid) * 15;
        float x1 = t[0], y1 = t[1], x2 = t[2], y2 = t[3];
        tX1[tid] = x1; tY1[tid] = y1; tX2[tid] = x2; tY2[tid] = y2;
        tA[tid] = (x2 - x1) * (y2 - y1);
        s_t[tid * 4 + 0] = x1; s_t[tid * 4 + 1] = y1;
        s_t[tid * 4 + 2] = x2; s_t[tid * 4 + 3] = y2;
#pragma unroll
        for (int j = 0; j < 10; j++) s_lm[tid * 10 + j] = t[4 + j];
        s_lab[tid] = (int)t[14];
        unsigned long long key = g_bp[b * ON + tid];
        unsigned j = 0xFFFFFFFFu - (unsigned)(key & 0xFFFFFFFFull);
        int v = (__uint_as_float((unsigned)(key >> 32)) >= 0.2f);
        s_js[tid] = j;
        s_vld[tid] = v;
        unsigned rel = j - (unsigned)pg0;
        if (rel < (unsigned)n) atomicOr(&s_bmp[rel >> 5], 1u << (rel & 31));
        unsigned bal = __ballot_sync(FULLMASK, v != 0);
        if (lane == 0) s_anyb[wid] = bal;
    }
    if (tid >= 64 && tid < 144) {
        int j = tid - 64;
        if (j < f) {
            float4 q = priors[base + j];
            float a = q.x - q.z * 0.5f, c = q.x + q.z * 0.5f;
            s_px1[j] = a; s_px2[j] = c; s_dx[j] = c - a;
        }
    }
    if (tid >= 160 && tid < 192) {
        int r = tid - 160;
        if (r < nrows) {
            float4 q = priors[base + (i0 + r) * f];
            float a = q.y - q.w * 0.5f, c = q.y + q.w * 0.5f;
            s_py1[r] = a; s_py2[r] = c; s_dy[r] = c - a;
        }
    }
    __syncthreads();

    if (!(s_anyb[0] | s_anyb[1])) return;   // batch contributes nothing

    const float S2 = s_dx[0] * s_dy[0];

    for (int o = wid; o < ON; o += 8) {
        float X1 = tX1[o], X2 = tX2[o];
        for (int j = lane; j < f; j += 32)
            s_wx[o * 80 + j] = fmaxf(fminf(X2, s_px2[j]) - fmaxf(X1, s_px1[j]), 0.f);
        float Y1 = tY1[o], Y2 = tY2[o];
        float C = tA[o] + S2;
        float invC = __fdiv_rn(1.f, C);
        if (lane == 0) s_C[o] = C;
        if (lane < 28) {
            float wy = (lane < nrows)
                ? fmaxf(fminf(Y2, s_py2[lane]) - fmaxf(Y1, s_py1[lane]), 0.f)
                : 0.f;
            s_wyc[o * 28 + lane] = wy * invC;
        }
    }
    __syncthreads();

    if (tid < 32) {
        float ylo = s_py1[0], yhi = s_py2[nrows - 1];
        unsigned lml = (1u << tid) - 1u;
        int o1 = tid, o2 = tid + 32;
        bool k1 = (tY1[o1] < yhi) && (tY2[o1] > ylo);
        bool k2 = (tY1[o2] < yhi) && (tY2[o2] > ylo);
        unsigned m1 = __ballot_sync(FULLMASK, k1);
        unsigned m2 = __ballot_sync(FULLMASK, k2);
        int n1 = __popc(m1);
        if (k1) { int d = __popc(m1 & lml); cO[d] = o1; }
        if (k2) { int d = n1 + __popc(m2 & lml); cO[d] = o2; }
        if (tid == 0) s_cnt = n1 + __popc(m2);
    }
    __syncthreads();

    const int t4 = 4 * tid;
    const bool act = (t4 < n);
    int rr = 27, j0 = 0;
    if (act) {
        int gi = off + t4;
        int i = gi / f;
        j0 = gi - i * f;
        rr = i - i0;
    }
    float bs0 = 0.f, bs1 = 0.f, bs2 = 0.f, bs3 = 0.f;
    int bo0 = 0, bo1 = 0, bo2 = 0, bo3 = 0;

    const int cnt = s_cnt;
    for (int c = 0; c < cnt; c++) {
        const int oid = cO[c];
        const float wyc = s_wyc[oid * 28 + rr];
        if (wyc == 0.f) continue;
        const float4 wx4 = *(const float4*)&s_wx[oid * 80 + j0];
        float sc0 = wx4.x * wyc, sc1 = wx4.y * wyc;
        float sc2 = wx4.z * wyc, sc3 = wx4.w * wyc;
        if (sc0 > bs0) { bs0 = sc0; bo0 = oid; }
        if (sc1 > bs1) { bs1 = sc1; bo1 = oid; }
        if (sc2 > bs2) { bs2 = sc2; bo2 = oid; }
        if (sc3 > bs3) { bs3 = sc3; bo3 = oid; }
    }

    // ---------- inline loss phase A for own 4 priors ----------
    float ll = 0.f, llm = 0.f, cep = 0.f;
    int np = 0, np1 = 0;

    if (act) {
        float ovk[4]; int okk[4] = {bo0, bo1, bo2, bo3};
        const float py1r = s_py1[rr], py2r = s_py2[rr];
#pragma unroll
        for (int k = 0; k < 4; k++) {
            int o = okk[k];
            float wy = fmaxf(fminf(tY2[o], py2r) - fmaxf(tY1[o], py1r), 0.f);
            float inter = s_wx[o * 80 + j0 + k] * wy;
            float den = s_C[o] - inter;
            ovk[k] = __fdiv_rn(inter, den);
        }
        // scatter corrections via range bitmap
        unsigned bmw = (s_bmp[t4 >> 5] >> (t4 & 31)) & 0xFu;
        if (bmw) {
#pragma unroll
            for (int k = 0; k < 4; k++) {
                if ((bmw >> k) & 1u) {
                    unsigned p = (unsigned)(pg0 + t4 + k);
                    int oo = 0;
                    for (int o = 0; o < ON; o++)
                        if (s_js[o] == p) oo = o;       // last writer wins
                    okk[k] = oo;
                    if (s_vld[oo]) ovk[k] = 2.0f;
                }
            }
        }

        const float4* cf4 = (const float4*)(conf + ((size_t)b * PN + (pg0 + t4)) * 2);
        float4 cfa = cf4[0], cfb = cf4[1];
        float c0k[4] = {cfa.x, cfa.z, cfb.x, cfb.z};
        float c1k[4] = {cfa.y, cfa.w, cfb.y, cfb.w};

        float rk[4];
#pragma unroll
        for (int k = 0; k < 4; k++) {
            const int p = pg0 + t4 + k;
            int c = (ovk[k] < 0.35f) ? 0 : s_lab[okk[k]];
            bool pos = (c != 0);
            float c0 = c0k[k], c1 = c1k[k];
            if (pos) {
                np++;
                int o = okk[k];
                float4 q = priors[p];
                float m0 = s_t[o * 4 + 0], m1 = s_t[o * 4 + 1];
                float m2 = s_t[o * 4 + 2], m3 = s_t[o * 4 + 3];
                float isx = 0.1f * q.z, isy = 0.1f * q.w;
                float gx = ((m0 + m2) * 0.5f - q.x) / isx;
                float gy = ((m1 + m3) * 0.5f - q.y) / isy;
                float gw = logf((m2 - m0) / q.z) * 5.0f;
                float gh = logf((m3 - m1) / q.w) * 5.0f;
                const float4 L = *(const float4*)(loc + ((size_t)b * PN + p) * 4);
                ll += sl1(L.x - gx) + sl1(L.y - gy) + sl1(L.z - gw) + sl1(L.w - gh);
                if (c > 0) {
                    np1++;
                    const float* D = landm + ((size_t)b * PN + p) * 10;
#pragma unroll
                    for (int j = 0; j < 5; j++) {
                        float lx = (s_lm[o * 10 + 2 * j]     - q.x) / isx;
                        float ly = (s_lm[o * 10 + 2 * j + 1] - q.y) / isy;
                        llm += sl1(D[2 * j] - lx) + sl1(D[2 * j + 1] - ly);
                    }
                }
            }
            float mx = fmaxf(c0, c1), mn = fminf(c0, c1);
            float lse = mx + __logf(1.f + __expf(mn - mx));
            float ce = lse - (pos ? c1 : c0);
            if (pos) cep += ce;
            rk[k] = pos ? 0.f : ce;
        }
        *(float4*)&g_rank[(size_t)b * PN + pg0 + t4] = make_float4(rk[0], rk[1], rk[2], rk[3]);
    }

    float wll = warp_sumf(ll), wlm = warp_sumf(llm), wce = warp_sumf(cep);
    int wnp = warp_sumi(np), wnp1 = warp_sumi(np1);
    if (lane == 0) {
        atomicAdd(&r_ll, wll); atomicAdd(&r_lm, wlm); atomicAdd(&r_ce, wce);
        atomicAdd(&r_np, wnp); atomicAdd(&r_np1, wnp1);
    }
    __syncthreads();
    if (tid == 0) {
        if (r_ll != 0.f) atomicAdd(&g_acc[0], r_ll);
        if (r_ce != 0.f) atomicAdd(&g_acc[1], r_ce);
        if (r_lm != 0.f) atomicAdd(&g_acc[2], r_lm);
        if (r_np)  { atomicAdd(&g_cnt[0], r_np); atomicAdd(&g_npb[b], r_np); }
        if (r_np1) atomicAdd(&g_cnt[1], r_np1);
    }
}

// =================== k_B: top-k select + sum + finalize ===================
#define N4   (PN / 4)
#define PADN (17 * 1024)
#define CAP  8400

__global__ void __launch_bounds__(1024, 1) k_B(float* __restrict__ out)
{
    const int b = blockIdx.x;
    const int tid = threadIdx.x;
    const int lane = tid & 31;
    const int warp = tid >> 5;

    __shared__ unsigned cand[CAP];
    __shared__ unsigned hist[2048];
    __shared__ unsigned s_wsum[32];
    __shared__ float s_sum, s_above;
    __shared__ int s_cgt, s_krm, s_cc;
    __shared__ unsigned s_selbin, s_selA, s_selB, s_mcnt;

    const int np = g_npb[b];
    const int k = min(7 * np, PN - 1);

    if (k > 0) {
        if (tid == 0) { s_sum = 0.f; s_above = 0.f; s_cgt = 0; s_cc = 0; }
        for (int i = tid; i < 2048; i += 1024) hist[i] = 0;
        __syncthreads();

        const float* grank = g_rank + (size_t)b * PN;
        const float4* grank4 = (const float4*)grank;

        // scan 1: 11-bit histogram (match_any aggregated, padded)
        for (int p = tid; p < PADN; p += 1024) {
            bool in = (p < PN);
            unsigned v = in ? __float_as_uint(grank[p]) : 0u;
            unsigned bin = v >> 21;
            unsigned okm = __ballot_sync(FULLMASK, in);
            unsigned peers = __match_any_sync(FULLMASK, bin) & okm;
            if (in && (lane == __ffs(peers) - 1))
                atomicAdd(&hist[bin], (unsigned)__popc(peers));
        }
        __syncthreads();

        select_desc<2048>(hist, s_wsum, k, &s_krm, &s_selbin, tid, lane, warp);
        if (tid == 0) s_mcnt = hist[s_selbin];
        __syncthreads();

        const unsigned selbin = s_selbin;
        const unsigned m = s_mcnt;
        const int kr0 = s_krm;
        float tval, topsum;

        if (m <= CAP) {
            // scan 2: above-bin sum + compact selected bin
            float la = 0.f;
            for (int i = tid; i < N4; i += 1024) {
                float4 v4 = grank4[i];
                float vk[4] = {v4.x, v4.y, v4.z, v4.w};
#pragma unroll
                for (int kk = 0; kk < 4; kk++) {
                    unsigned u = __float_as_uint(vk[kk]);
                    unsigned bn = u >> 21;
                    if (bn > selbin) la += vk[kk];
                    else if (bn == selbin) cand[atomicAdd(&s_cc, 1)] = u;
                }
            }
            la = warp_sumf(la);
            if (lane == 0) atomicAdd(&s_above, la);
            for (int i = tid; i < 2048; i += 1024) hist[i] = 0;
            __syncthreads();

            for (int i = tid; i < (int)m; i += 1024)
                atomicAdd(&hist[(cand[i] >> 10) & 2047u], 1u);
            __syncthreads();
            select_desc<2048>(hist, s_wsum, kr0, &s_krm, &s_selA, tid, lane, warp);

            const unsigned selA = s_selA;
            if (tid < 1024) hist[tid] = 0;
            __syncthreads();

            for (int i = tid; i < (int)m; i += 1024) {
                unsigned v = cand[i];
                if (((v >> 10) & 2047u) == selA) atomicAdd(&hist[v & 1023u], 1u);
            }
            __syncthreads();
            select_desc<1024>(hist, s_wsum, s_krm, &s_krm, &s_selB, tid, lane, warp);

            tval = __uint_as_float((selbin << 21) | (selA << 10) | s_selB);

            float ls = 0.f; int lc = 0;
            for (int i = tid; i < (int)m; i += 1024) {
                float v = __uint_as_float(cand[i]);
                if (v > tval) { ls += v; lc++; }
            }
            ls = warp_sumf(ls); lc = warp_sumi(lc);
            if (lane == 0) { atomicAdd(&s_sum, ls); atomicAdd(&s_cgt, lc); }
            __syncthreads();
            topsum = s_above + s_sum + (float)(kr0 - s_cgt) * tval;
        } else {
            // fallback: full-scan sparse passes
            for (int i = tid; i < 2048; i += 1024) hist[i] = 0;
            __syncthreads();
            for (int i = tid; i < N4; i += 1024) {
                float4 v4 = grank4[i];
                float vk[4] = {v4.x, v4.y, v4.z, v4.w};
#pragma unroll
                for (int kk = 0; kk < 4; kk++) {
                    unsigned u = __float_as_uint(vk[kk]);
                    if ((u >> 21) == selbin) atomicAdd(&hist[(u >> 10) & 2047u], 1u);
                }
            }
            __syncthreads();
            select_desc<2048>(hist, s_wsum, kr0, &s_krm, &s_selA, tid, lane, warp);

            const unsigned pref1 = (selbin << 11) | s_selA;
            if (tid < 1024) hist[tid] = 0;
            __syncthreads();
            for (int i = tid; i < N4; i += 1024) {
                float4 v4 = grank4[i];
                float vk[4] = {v4.x, v4.y, v4.z, v4.w};
#pragma unroll
                for (int kk = 0; kk < 4; kk++) {
                    unsigned u = __float_as_uint(vk[kk]);
                    if ((u >> 10) == pref1) atomicAdd(&hist[u & 1023u], 1u);
                }
            }
            __syncthreads();
            select_desc<1024>(hist, s_wsum, s_krm, &s_krm, &s_selB, tid, lane, warp);

            tval = __uint_as_float((pref1 << 10) | s_selB);

            float ls = 0.f; int lc = 0;
            for (int i = tid; i < N4; i += 1024) {
                float4 v4 = grank4[i];
                if (v4.x > tval) { ls += v4.x; lc++; }
                if (v4.y > tval) { ls += v4.y; lc++; }
                if (v4.z > tval) { ls += v4.z; lc++; }
                if (v4.w > tval) { ls += v4.w; lc++; }
            }
            ls = warp_sumf(ls); lc = warp_sumi(lc);
            if (lane == 0) { atomicAdd(&s_sum, ls); atomicAdd(&s_cgt, lc); }
            __syncthreads();
            topsum = s_sum + (float)(k - s_cgt) * tval;
        }

        if (tid == 0)
            atomicAdd(&g_acc[1], topsum);
    }

    // ---- last-block finalize (64 tickets) ----
    __syncthreads();
    if (tid == 0) {
        __threadfence();
        int t = atomicAdd(&g_done, 1);
        if (t == BN - 1) {
            float a0 = *(volatile float*)&g_acc[0];
            float a1 = *(volatile float*)&g_acc[1];
            float a2 = *(volatile float*)&g_acc[2];
            int c0 = *(volatile int*)&g_cnt[0];
            int c1 = *(volatile int*)&g_cnt[1];
            out[0] = a0 / fmaxf((float)c0, 1.f);
            out[1] = a1 / fmaxf((float)c0, 1.f);
            out[2] = a2 / fmaxf((float)c1, 1.f);
            g_done = 0;
        }
    }
}

// =================== launch ===================
extern "C" void kernel_launch(void* const* d_in, const int* in_sizes, int n_in,
                              void* d_out, int out_size) {
    const float* loc = (const float*)d_in[0];
    const float* conf = (const float*)d_in[1];
    const float* landm = (const float*)d_in[2];
    const float4* priors = (const float4*)d_in[3];
    const float* targets = (const float*)d_in[4];
    float* out = (float*)d_out;

    k_pre<<<BN, 256>>>(priors, targets);
    dim3 gf(20, BN);
    k_fused<<<gf, 256>>>(loc, conf, landm, priors, targets);
    k_B<<<BN, 1024>>>(out);
}

// round 17
// speedup vs baseline: 1.1095x; 1.1095x over previous
#include <cuda_runtime.h>

#define PN 16800
#define ON 64
#define BN 64
#define FULLMASK 0xffffffffu

// ---------------- scratch ----------------
__device__ unsigned long long g_bp6[BN * ON * 6];  // per (batch,truth,grid) key; plain stores
__device__ float g_rank[BN * PN];
__device__ int g_npb[BN];
__device__ float g_acc[3];
__device__ int g_cnt[2];
__device__ int g_done;

// =================== helpers ===================
__device__ __forceinline__ float sl1(float x) {
    float a = fabsf(x);
    return a < 1.f ? 0.5f * a * a : a - 0.5f;
}
__device__ __forceinline__ float warp_sumf(float v) {
#pragma unroll
    for (int s = 16; s; s >>= 1) v += __shfl_xor_sync(FULLMASK, v, s);
    return v;
}
__device__ __forceinline__ int warp_sumi(int v) {
#pragma unroll
    for (int s = 16; s; s >>= 1) v += __shfl_xor_sync(FULLMASK, v, s);
    return v;
}

template<int NB>
__device__ __forceinline__ void select_desc(
    unsigned* hist, unsigned* s_wsum,
    int kr_in, int* s_kr, unsigned* s_sel,
    int tid, int lane, int warp)
{
    if (NB == 2048) {
        unsigned h0 = hist[2047 - 2 * tid];
        unsigned h1 = hist[2046 - 2 * tid];
        unsigned sv = h0 + h1, inc = sv;
#pragma unroll
        for (int d = 1; d < 32; d <<= 1) {
            unsigned ot = __shfl_up_sync(FULLMASK, inc, d);
            if (lane >= d) inc += ot;
        }
        if (lane == 31) s_wsum[warp] = inc;
        __syncthreads();
        if (tid < 32) {
            unsigned w = s_wsum[tid], wi = w;
#pragma unroll
            for (int d = 1; d < 32; d <<= 1) {
                unsigned ot = __shfl_up_sync(FULLMASK, wi, d);
                if (tid >= d) wi += ot;
            }
            s_wsum[tid] = wi - w;
        }
        __syncthreads();
        unsigned excl = s_wsum[warp] + (inc - sv);
        unsigned kr = (unsigned)kr_in;
        bool x0 = (excl < kr) && (excl + h0 >= kr);
        bool x1 = (excl + h0 < kr) && (excl + h0 + h1 >= kr);
        __syncthreads();
        if (x0) { *s_kr = (int)(kr - excl); *s_sel = (unsigned)(2047 - 2 * tid); }
        if (x1) { *s_kr = (int)(kr - excl - h0); *s_sel = (unsigned)(2046 - 2 * tid); }
        __syncthreads();
    } else {
        unsigned h0 = hist[1023 - tid];
        unsigned inc = h0;
#pragma unroll
        for (int d = 1; d < 32; d <<= 1) {
            unsigned ot = __shfl_up_sync(FULLMASK, inc, d);
            if (lane >= d) inc += ot;
        }
        if (lane == 31) s_wsum[warp] = inc;
        __syncthreads();
        if (tid < 32) {
            unsigned w = s_wsum[tid], wi = w;
#pragma unroll
            for (int d = 1; d < 32; d <<= 1) {
                unsigned ot = __shfl_up_sync(FULLMASK, wi, d);
                if (tid >= d) wi += ot;
            }
            s_wsum[tid] = wi - w;
        }
        __syncthreads();
        unsigned excl = s_wsum[warp] + (inc - h0);
        unsigned kr = (unsigned)kr_in;
        bool x0 = (excl < kr) && (excl + h0 >= kr);
        __syncthreads();
        if (x0) { *s_kr = (int)(kr - excl); *s_sel = (unsigned)(1023 - tid); }
        __syncthreads();
    }
}

// ============ k_pre: best prior per (truth, grid) — grid (6, BN) ============
__global__ void __launch_bounds__(256) k_pre(
    const float4* __restrict__ priors,
    const float* __restrict__ targets)
{
    const int g = blockIdx.x;
    const int b = blockIdx.y;
    const int tid = threadIdx.x;
    const int lane = tid & 31;
    const int wid = tid >> 5;

    const int f    = (g < 2) ? 80 : (g < 4) ? 40 : 20;
    const int base = (g == 0) ? 0 : (g == 1) ? 6400 : (g == 2) ? 12800 :
                     (g == 3) ? 14400 : (g == 4) ? 16000 : 16400;

    __shared__ float tX1[ON], tX2[ON], tY1[ON], tY2[ON], tA[ON];
    __shared__ float px1[80], px2[80], py1[80], py2[80];

    if (tid < ON) {
        const float* t = targets + (size_t)(b * ON + tid) * 15;
        float x1 = t[0], y1 = t[1], x2 = t[2], y2 = t[3];
        tX1[tid] = x1; tY1[tid] = y1; tX2[tid] = x2; tY2[tid] = y2;
        tA[tid] = (x2 - x1) * (y2 - y1);
    }
    if (tid >= 64 && tid < 64 + 80) {
        int j = tid - 64;
        if (j < f) {
            float4 q = priors[base + j];
            px1[j] = q.x - q.z * 0.5f; px2[j] = q.x + q.z * 0.5f;
        }
    }
    if (tid >= 144 && tid < 144 + 80) {
        int r = tid - 144;
        if (r < f) {
            float4 q = priors[base + r * f];
            py1[r] = q.y - q.w * 0.5f; py2[r] = q.y + q.w * 0.5f;
        }
    }
    // resets (same-value benign races across b)
    if (g == 0) {
        if (tid < 3) g_acc[tid] = 0.f;
        if (tid >= 3 && tid < 5) g_cnt[tid - 3] = 0;
        if (tid == 5) g_npb[b] = 0;
    }
    __syncthreads();

    for (int it = 0; it < 8; it++) {
        const int o = wid * 8 + it;
        const float X1 = tX1[o], X2 = tX2[o], Y1 = tY1[o], Y2 = tY2[o], A = tA[o];
        float bwx = -1.f; int bj = lane;
        for (int j = lane; j < f; j += 32) {
            float v = fmaxf(fminf(X2, px2[j]) - fmaxf(X1, px1[j]), 0.f);
            if (v > bwx) { bwx = v; bj = j; }
        }
        float bwy = -1.f; int bi2 = lane;
        for (int i = lane; i < f; i += 32) {
            float v = fmaxf(fminf(Y2, py2[i]) - fmaxf(Y1, py1[i]), 0.f);
            if (v > bwy) { bwy = v; bi2 = i; }
        }
#pragma unroll
        for (int s = 16; s; s >>= 1) {
            float ov = __shfl_xor_sync(FULLMASK, bwx, s);
            int oj = __shfl_xor_sync(FULLMASK, bj, s);
            if (ov > bwx || (ov == bwx && oj < bj)) { bwx = ov; bj = oj; }
            float ov2 = __shfl_xor_sync(FULLMASK, bwy, s);
            int oi = __shfl_xor_sync(FULLMASK, bi2, s);
            if (ov2 > bwy || (ov2 == bwy && oi < bi2)) { bwy = ov2; bi2 = oi; }
        }
        if (lane == 0) {
            float P = bwx * bwy;
            float dx = px2[bj] - px1[bj];
            float dy = py2[bi2] - py1[bi2];
            float den = (A + dx * dy) - P;
            float iou = __fdiv_rn(P, den);
            unsigned pidx = (unsigned)(base + bi2 * f + bj);
            unsigned long long key =
                ((unsigned long long)__float_as_uint(iou) << 32) |
                (unsigned long long)(0xFFFFFFFFu - pidx);
            g_bp6[(size_t)(b * ON + o) * 6 + g] = key;
        }
    }
}

// =================== k_fused: match tiles + inline loss phase A ===========
__global__ void __launch_bounds__(256) k_fused(
    const float* __restrict__ loc,
    const float* __restrict__ conf,
    const float* __restrict__ landm,
    const float4* __restrict__ priors,
    const float* __restrict__ targets)
{
    const int b = blockIdx.y;
    const int bx = blockIdx.x;
    const int tid = threadIdx.x;
    const int lane = tid & 31;
    const int wid = tid >> 5;

    int g, blk;
    if (bx < 7)       { g = 0; blk = bx; }
    else if (bx < 14) { g = 1; blk = bx - 7; }
    else if (bx < 16) { g = 2; blk = bx - 14; }
    else if (bx < 18) { g = 3; blk = bx - 16; }
    else if (bx == 18){ g = 4; blk = 0; }
    else              { g = 5; blk = 0; }
    const int f    = (g < 2) ? 80 : (g < 4) ? 40 : 20;
    const int base = (g == 0) ? 0 : (g == 1) ? 6400 : (g == 2) ? 12800 :
                     (g == 3) ? 14400 : (g == 4) ? 16000 : 16400;
    const int off  = blk * 1024;
    const int n    = min(1024, f * f - off);
    const int i0   = off / f;
    const int nrows = (off + n - 1) / f - i0 + 1;
    const int pg0  = base + off;

    __shared__ float tX1[ON], tX2[ON], tY1[ON], tY2[ON], tA[ON];
    __shared__ float s_wx[ON * 80];
    __shared__ float s_wyc[ON * 28];
    __shared__ float s_C[ON];
    __shared__ float s_px1[80], s_px2[80], s_dx[80];
    __shared__ float s_py1[28], s_py2[28], s_dy[28];
    __shared__ float s_t[ON * 4];
    __shared__ float s_lm[ON * 10];
    __shared__ int s_lab[ON];
    __shared__ unsigned s_js[ON];
    __shared__ int s_vld[ON];
    __shared__ unsigned s_bmp[32];
    __shared__ unsigned s_anyb[2];
    __shared__ int cO[ON];
    __shared__ int s_cnt;
    __shared__ float r_ll, r_lm, r_ce;
    __shared__ int r_np, r_np1;

    if (tid < 32) s_bmp[tid] = 0;
    if (tid == 0) { r_ll = 0.f; r_lm = 0.f; r_ce = 0.f; r_np = 0; r_np1 = 0; }

    if (tid < ON) {
        const float* t = targets + (size_t)(b * ON + tid) * 15;
        float x1 = t[0], y1 = t[1], x2 = t[2], y2 = t[3];
        tX1[tid] = x1; tY1[tid] = y1; tX2[tid] = x2; tY2[tid] = y2;
        tA[tid] = (x2 - x1) * (y2 - y1);
        s_t[tid * 4 + 0] = x1; s_t[tid * 4 + 1] = y1;
        s_t[tid * 4 + 2] = x2; s_t[tid * 4 + 3] = y2;
#pragma unroll
        for (int j = 0; j < 10; j++) s_lm[tid * 10 + j] = t[4 + j];
        s_lab[tid] = (int)t[14];
        // combine per-grid keys (replaces atomicMax'd g_bp)
        unsigned long long key = 0ull;
#pragma unroll
        for (int gg = 0; gg < 6; gg++) {
            unsigned long long v = g_bp6[(size_t)(b * ON + tid) * 6 + gg];
            if (v > key) key = v;
        }
        unsigned j = 0xFFFFFFFFu - (unsigned)(key & 0xFFFFFFFFull);
        int v = (__uint_as_float((unsigned)(key >> 32)) >= 0.2f);
        s_js[tid] = j;
        s_vld[tid] = v;
        unsigned rel = j - (unsigned)pg0;
        if (rel < (unsigned)n) atomicOr(&s_bmp[rel >> 5], 1u << (rel & 31));
        unsigned bal = __ballot_sync(FULLMASK, v != 0);
        if (lane == 0) s_anyb[wid] = bal;
    }
    if (tid >= 64 && tid < 144) {
        int j = tid - 64;
        if (j < f) {
            float4 q = priors[base + j];
            float a = q.x - q.z * 0.5f, c = q.x + q.z * 0.5f;
            s_px1[j] = a; s_px2[j] = c; s_dx[j] = c - a;
        }
    }
    if (tid >= 160 && tid < 192) {
        int r = tid - 160;
        if (r < nrows) {
            float4 q = priors[base + (i0 + r) * f];
            float a = q.y - q.w * 0.5f, c = q.y + q.w * 0.5f;
            s_py1[r] = a; s_py2[r] = c; s_dy[r] = c - a;
        }
    }
    __syncthreads();

    if (!(s_anyb[0] | s_anyb[1])) return;

    const float S2 = s_dx[0] * s_dy[0];

    for (int o = wid; o < ON; o += 8) {
        float X1 = tX1[o], X2 = tX2[o];
        for (int j = lane; j < f; j += 32)
            s_wx[o * 80 + j] = fmaxf(fminf(X2, s_px2[j]) - fmaxf(X1, s_px1[j]), 0.f);
        float Y1 = tY1[o], Y2 = tY2[o];
        float C = tA[o] + S2;
        float invC = __fdiv_rn(1.f, C);
        if (lane == 0) s_C[o] = C;
        if (lane < 28) {
            float wy = (lane < nrows)
                ? fmaxf(fminf(Y2, s_py2[lane]) - fmaxf(Y1, s_py1[lane]), 0.f)
                : 0.f;
            s_wyc[o * 28 + lane] = wy * invC;
        }
    }
    __syncthreads();

    if (tid < 32) {
        float ylo = s_py1[0], yhi = s_py2[nrows - 1];
        unsigned lml = (1u << tid) - 1u;
        int o1 = tid, o2 = tid + 32;
        bool k1 = (tY1[o1] < yhi) && (tY2[o1] > ylo);
        bool k2 = (tY1[o2] < yhi) && (tY2[o2] > ylo);
        unsigned m1 = __ballot_sync(FULLMASK, k1);
        unsigned m2 = __ballot_sync(FULLMASK, k2);
        int n1 = __popc(m1);
        if (k1) { int d = __popc(m1 & lml); cO[d] = o1; }
        if (k2) { int d = n1 + __popc(m2 & lml); cO[d] = o2; }
        if (tid == 0) s_cnt = n1 + __popc(m2);
    }
    __syncthreads();

    const int t4 = 4 * tid;
    const bool act = (t4 < n);
    int rr = 27, j0 = 0;
    if (act) {
        int gi = off + t4;
        int i = gi / f;
        j0 = gi - i * f;
        rr = i - i0;
    }
    float bs0 = 0.f, bs1 = 0.f, bs2 = 0.f, bs3 = 0.f;
    int bo0 = 0, bo1 = 0, bo2 = 0, bo3 = 0;

    const int cnt = s_cnt;
    for (int c = 0; c < cnt; c++) {
        const int oid = cO[c];
        const float wyc = s_wyc[oid * 28 + rr];
        if (wyc == 0.f) continue;
        const float4 wx4 = *(const float4*)&s_wx[oid * 80 + j0];
        float sc0 = wx4.x * wyc, sc1 = wx4.y * wyc;
        float sc2 = wx4.z * wyc, sc3 = wx4.w * wyc;
        if (sc0 > bs0) { bs0 = sc0; bo0 = oid; }
        if (sc1 > bs1) { bs1 = sc1; bo1 = oid; }
        if (sc2 > bs2) { bs2 = sc2; bo2 = oid; }
        if (sc3 > bs3) { bs3 = sc3; bo3 = oid; }
    }

    // ---------- inline loss phase A ----------
    float ll = 0.f, llm = 0.f, cep = 0.f;
    int np = 0, np1 = 0;

    if (act) {
        float ovk[4]; int okk[4] = {bo0, bo1, bo2, bo3};
        const float py1r = s_py1[rr], py2r = s_py2[rr];
#pragma unroll
        for (int k = 0; k < 4; k++) {
            int o = okk[k];
            float wy = fmaxf(fminf(tY2[o], py2r) - fmaxf(tY1[o], py1r), 0.f);
            float inter = s_wx[o * 80 + j0 + k] * wy;
            float den = s_C[o] - inter;
            ovk[k] = __fdiv_rn(inter, den);
        }
        unsigned bmw = (s_bmp[t4 >> 5] >> (t4 & 31)) & 0xFu;
        if (bmw) {
#pragma unroll
            for (int k = 0; k < 4; k++) {
                if ((bmw >> k) & 1u) {
                    unsigned p = (unsigned)(pg0 + t4 + k);
                    int oo = 0;
                    for (int o = 0; o < ON; o++)
                        if (s_js[o] == p) oo = o;
                    okk[k] = oo;
                    if (s_vld[oo]) ovk[k] = 2.0f;
                }
            }
        }

        const float4* cf4 = (const float4*)(conf + ((size_t)b * PN + (pg0 + t4)) * 2);
        float4 cfa = cf4[0], cfb = cf4[1];
        float c0k[4] = {cfa.x, cfa.z, cfb.x, cfb.z};
        float c1k[4] = {cfa.y, cfa.w, cfb.y, cfb.w};

        float rk[4];
#pragma unroll
        for (int k = 0; k < 4; k++) {
            const int p = pg0 + t4 + k;
            int c = (ovk[k] < 0.35f) ? 0 : s_lab[okk[k]];
            bool pos = (c != 0);
            float c0 = c0k[k], c1 = c1k[k];
            if (pos) {
                np++;
                int o = okk[k];
                float4 q = priors[p];
                float m0 = s_t[o * 4 + 0], m1 = s_t[o * 4 + 1];
                float m2 = s_t[o * 4 + 2], m3 = s_t[o * 4 + 3];
                float isx = 0.1f * q.z, isy = 0.1f * q.w;
                float gx = ((m0 + m2) * 0.5f - q.x) / isx;
                float gy = ((m1 + m3) * 0.5f - q.y) / isy;
                float gw = logf((m2 - m0) / q.z) * 5.0f;
                float gh = logf((m3 - m1) / q.w) * 5.0f;
                const float4 L = *(const float4*)(loc + ((size_t)b * PN + p) * 4);
                ll += sl1(L.x - gx) + sl1(L.y - gy) + sl1(L.z - gw) + sl1(L.w - gh);
                if (c > 0) {
                    np1++;
                    const float* D = landm + ((size_t)b * PN + p) * 10;
#pragma unroll
                    for (int j = 0; j < 5; j++) {
                        float lx = (s_lm[o * 10 + 2 * j]     - q.x) / isx;
                        float ly = (s_lm[o * 10 + 2 * j + 1] - q.y) / isy;
                        llm += sl1(D[2 * j] - lx) + sl1(D[2 * j + 1] - ly);
                    }
                }
            }
            float mx = fmaxf(c0, c1), mn = fminf(c0, c1);
            float lse = mx + __logf(1.f + __expf(mn - mx));
            float ce = lse - (pos ? c1 : c0);
            if (pos) cep += ce;
            rk[k] = pos ? 0.f : ce;
        }
        *(float4*)&g_rank[(size_t)b * PN + pg0 + t4] = make_float4(rk[0], rk[1], rk[2], rk[3]);
    }

    float wll = warp_sumf(ll), wlm = warp_sumf(llm), wce = warp_sumf(cep);
    int wnp = warp_sumi(np), wnp1 = warp_sumi(np1);
    if (lane == 0) {
        atomicAdd(&r_ll, wll); atomicAdd(&r_lm, wlm); atomicAdd(&r_ce, wce);
        atomicAdd(&r_np, wnp); atomicAdd(&r_np1, wnp1);
    }
    __syncthreads();
    if (tid == 0) {
        if (r_ll != 0.f) atomicAdd(&g_acc[0], r_ll);
        if (r_ce != 0.f) atomicAdd(&g_acc[1], r_ce);
        if (r_lm != 0.f) atomicAdd(&g_acc[2], r_lm);
        if (r_np)  { atomicAdd(&g_cnt[0], r_np); atomicAdd(&g_npb[b], r_np); }
        if (r_np1) atomicAdd(&g_cnt[1], r_np1);
    }
}

// =================== k_B: top-k select + sum + finalize ===================
#define N4   (PN / 4)
#define PADN (17 * 1024)
#define CAP  8400

__global__ void __launch_bounds__(1024, 1) k_B(float* __restrict__ out)
{
    const int b = blockIdx.x;
    const int tid = threadIdx.x;
    const int lane = tid & 31;
    const int warp = tid >> 5;

    __shared__ unsigned cand[CAP];
    __shared__ unsigned hist[2048];
    __shared__ unsigned s_wsum[32];
    __shared__ float s_sum, s_above;
    __shared__ int s_cgt, s_krm, s_cc;
    __shared__ unsigned s_selbin, s_selA, s_selB, s_mcnt;

    const int np = g_npb[b];
    const int k = min(7 * np, PN - 1);

    if (k > 0) {
        if (tid == 0) { s_sum = 0.f; s_above = 0.f; s_cgt = 0; s_cc = 0; }
        for (int i = tid; i < 2048; i += 1024) hist[i] = 0;
        __syncthreads();

        const float* grank = g_rank + (size_t)b * PN;
        const float4* grank4 = (const float4*)grank;

        for (int p = tid; p < PADN; p += 1024) {
            bool in = (p < PN);
            unsigned v = in ? __float_as_uint(grank[p]) : 0u;
            unsigned bin = v >> 21;
            unsigned okm = __ballot_sync(FULLMASK, in);
            unsigned peers = __match_any_sync(FULLMASK, bin) & okm;
            if (in && (lane == __ffs(peers) - 1))
                atomicAdd(&hist[bin], (unsigned)__popc(peers));
        }
        __syncthreads();

        select_desc<2048>(hist, s_wsum, k, &s_krm, &s_selbin, tid, lane, warp);
        if (tid == 0) s_mcnt = hist[s_selbin];
        __syncthreads();

        const unsigned selbin = s_selbin;
        const unsigned m = s_mcnt;
        const int kr0 = s_krm;
        float tval, topsum;

        if (m <= CAP) {
            float la = 0.f;
            for (int i = tid; i < N4; i += 1024) {
                float4 v4 = grank4[i];
                float vk[4] = {v4.x, v4.y, v4.z, v4.w};
#pragma unroll
                for (int kk = 0; kk < 4; kk++) {
                    unsigned u = __float_as_uint(vk[kk]);
                    unsigned bn = u >> 21;
                    if (bn > selbin) la += vk[kk];
                    else if (bn == selbin) cand[atomicAdd(&s_cc, 1)] = u;
                }
            }
            la = warp_sumf(la);
            if (lane == 0) atomicAdd(&s_above, la);
            for (int i = tid; i < 2048; i += 1024) hist[i] = 0;
            __syncthreads();

            for (int i = tid; i < (int)m; i += 1024)
                atomicAdd(&hist[(cand[i] >> 10) & 2047u], 1u);
            __syncthreads();
            select_desc<2048>(hist, s_wsum, kr0, &s_krm, &s_selA, tid, lane, warp);

            const unsigned selA = s_selA;
            if (tid < 1024) hist[tid] = 0;
            __syncthreads();

            for (int i = tid; i < (int)m; i += 1024) {
                unsigned v = cand[i];
                if (((v >> 10) & 2047u) == selA) atomicAdd(&hist[v & 1023u], 1u);
            }
            __syncthreads();
            select_desc<1024>(hist, s_wsum, s_krm, &s_krm, &s_selB, tid, lane, warp);

            tval = __uint_as_float((selbin << 21) | (selA << 10) | s_selB);

            float ls = 0.f; int lc = 0;
            for (int i = tid; i < (int)m; i += 1024) {
                float v = __uint_as_float(cand[i]);
                if (v > tval) { ls += v; lc++; }
            }
            ls = warp_sumf(ls); lc = warp_sumi(lc);
            if (lane == 0) { atomicAdd(&s_sum, ls); atomicAdd(&s_cgt, lc); }
            __syncthreads();
            topsum = s_above + s_sum + (float)(kr0 - s_cgt) * tval;
        } else {
            for (int i = tid; i < 2048; i += 1024) hist[i] = 0;
            __syncthreads();
            for (int i = tid; i < N4; i += 1024) {
                float4 v4 = grank4[i];
                float vk[4] = {v4.x, v4.y, v4.z, v4.w};
#pragma unroll
                for (int kk = 0; kk < 4; kk++) {
                    unsigned u = __float_as_uint(vk[kk]);
                    if ((u >> 21) == selbin) atomicAdd(&hist[(u >> 10) & 2047u], 1u);
                }
            }
            __syncthreads();
            select_desc<2048>(hist, s_wsum, kr0, &s_krm, &s_selA, tid, lane, warp);

            const unsigned pref1 = (selbin << 11) | s_selA;
            if (tid < 1024) hist[tid] = 0;
            __syncthreads();
            for (int i = tid; i < N4; i += 1024) {
                float4 v4 = grank4[i];
                float vk[4] = {v4.x, v4.y, v4.z, v4.w};
#pragma unroll
                for (int kk = 0; kk < 4; kk++) {
                    unsigned u = __float_as_uint(vk[kk]);
                    if ((u >> 10) == pref1) atomicAdd(&hist[u & 1023u], 1u);
                }
            }
            __syncthreads();
            select_desc<1024>(hist, s_wsum, s_krm, &s_krm, &s_selB, tid, lane, warp);

            tval = __uint_as_float((pref1 << 10) | s_selB);

            float ls = 0.f; int lc = 0;
            for (int i = tid; i < N4; i += 1024) {
                float4 v4 = grank4[i];
                if (v4.x > tval) { ls += v4.x; lc++; }
                if (v4.y > tval) { ls += v4.y; lc++; }
                if (v4.z > tval) { ls += v4.z; lc++; }
                if (v4.w > tval) { ls += v4.w; lc++; }
            }
            ls = warp_sumf(ls); lc = warp_sumi(lc);
            if (lane == 0) { atomicAdd(&s_sum, ls); atomicAdd(&s_cgt, lc); }
            __syncthreads();
            topsum = s_sum + (float)(k - s_cgt) * tval;
        }

        if (tid == 0)
            atomicAdd(&g_acc[1], topsum);
    }

    __syncthreads();
    if (tid == 0) {
        __threadfence();
        int t = atomicAdd(&g_done, 1);
        if (t == BN - 1) {
            float a0 = *(volatile float*)&g_acc[0];
            float a1 = *(volatile float*)&g_acc[1];
            float a2 = *(volatile float*)&g_acc[2];
            int c0 = *(volatile int*)&g_cnt[0];
            int c1 = *(volatile int*)&g_cnt[1];
            out[0] = a0 / fmaxf((float)c0, 1.f);
            out[1] = a1 / fmaxf((float)c0, 1.f);
            out[2] = a2 / fmaxf((float)c1, 1.f);
            g_done = 0;
        }
    }
}

// =================== launch ===================
extern "C" void kernel_launch(void* const* d_in, const int* in_sizes, int n_in,
                              void* d_out, int out_size) {
    const float* loc = (const float*)d_in[0];
    const float* conf = (const float*)d_in[1];
    const float* landm = (const float*)d_in[2];
    const float4* priors = (const float4*)d_in[3];
    const float* targets = (const float*)d_in[4];
    float* out = (float*)d_out;

    dim3 gp(6, BN);
    k_pre<<<gp, 256>>>(priors, targets);
    dim3 gf(20, BN);
    k_fused<<<gf, 256>>>(loc, conf, landm, priors, targets);
    k_B<<<BN, 1024>>>(out);
}